// round 2
// baseline (speedup 1.0000x reference)
#include <cuda_runtime.h>

// YOLO loss: pred/target (bs, 7, 7, 30) f32 -> scalar f32.
// Single fused kernel: smem-staged coalesced streaming loads, per-cell compute,
// hierarchical reduction, last-block finalize (writes out, resets state for
// the next graph replay).

#define S_GRID 7
#define CH 30
#define CELLS_PER_BLOCK 128
#define NTHREADS 128

__device__ double g_acc = 0.0;
__device__ unsigned int g_counter = 0u;

__global__ __launch_bounds__(NTHREADS) void yolo_loss_kernel(
    const float* __restrict__ pred,
    const float* __restrict__ targ,
    int total_cells,
    float* __restrict__ out,
    double inv_bs)
{
    __shared__ float sp[CELLS_PER_BLOCK * CH];   // 15360 B
    __shared__ float st[CELLS_PER_BLOCK * CH];   // 15360 B
    __shared__ float warp_sums[NTHREADS / 32];

    const int tid = threadIdx.x;
    const long long cell0 = (long long)blockIdx.x * CELLS_PER_BLOCK;
    int ncells = total_cells - (int)cell0;
    if (ncells > CELLS_PER_BLOCK) ncells = CELLS_PER_BLOCK;

    const float* gpb = pred + cell0 * CH;
    const float* gtb = targ + cell0 * CH;

    if (ncells == CELLS_PER_BLOCK) {
        // Full tile: coalesced float4 staging with streaming (evict-first) loads.
        const float4* p4 = (const float4*)gpb;
        const float4* t4 = (const float4*)gtb;
        float4* sp4 = (float4*)sp;
        float4* st4 = (float4*)st;
        constexpr int NV4 = CELLS_PER_BLOCK * CH / 4;  // 960
        #pragma unroll
        for (int i = tid; i < NV4; i += NTHREADS) {
            sp4[i] = __ldcs(p4 + i);
            st4[i] = __ldcs(t4 + i);
        }
    } else {
        // Tail tile (rare): scalar copy of valid region only.
        const int nfl = ncells * CH;
        for (int i = tid; i < nfl; i += NTHREADS) {
            sp[i] = __ldcs(gpb + i);
            st[i] = __ldcs(gtb + i);
        }
    }
    __syncthreads();

    float loss = 0.0f;
    if (tid < ncells) {
        const float* p = sp + tid * CH;
        const float* t = st + tid * CH;

        const float obj = (t[4] > 0.0f) ? 1.0f : 0.0f;

        // no-object confidence loss (conf channels 4 and 9)
        const float dn0 = p[4] - t[4];
        const float dn1 = p[9] - t[9];
        const float noobj = dn0 * dn0 + dn1 * dn1;

        // class loss (channels 10..29)
        float cls = 0.0f;
        #pragma unroll
        for (int k = 10; k < 30; k++) {
            const float d = p[k] - t[k];
            cls = fmaf(d, d, cls);
        }

        // Target box 0 in xyxy (xy scaled by 1/S, wh raw)
        const float invS = 1.0f / (float)S_GRID;
        const float tx = t[0] * invS, ty = t[1] * invS;
        const float tw = t[2], th = t[3];
        const float tx0 = tx - 0.5f * tw, tx1 = tx + 0.5f * tw;
        const float ty0 = ty - 0.5f * th, ty1 = ty + 0.5f * th;
        const float area_t = tw * th;

        float iou0 = 0.0f, iou1 = 0.0f;
        #pragma unroll
        for (int b = 0; b < 2; b++) {
            const float* q = p + 5 * b;
            const float px = q[0] * invS, py = q[1] * invS;
            const float pw = q[2], ph = q[3];
            const float lx = fmaxf(px - 0.5f * pw, tx0);
            const float rx = fminf(px + 0.5f * pw, tx1);
            const float ly = fmaxf(py - 0.5f * ph, ty0);
            const float ry = fminf(py + 0.5f * ph, ty1);
            const float wx = fmaxf(rx - lx, 0.0f);
            const float wy = fmaxf(ry - ly, 0.0f);
            const float inter = wx * wy;
            const float uni = fmaxf(pw * ph + area_t - inter, 1e-10f);
            const float iou = inter / uni;
            if (b == 0) iou0 = iou; else iou1 = iou;
        }
        // jnp.argmax picks the first max -> b=1 only on strict greater.
        const int rb = (iou1 > iou0) ? 1 : 0;
        const float miou = fmaxf(iou0, iou1);

        const float* q  = p + 5 * rb;
        const float* tq = t + 5 * rb;
        const float dx = q[0] - tq[0];
        const float dy = q[1] - tq[1];
        const float lxy = dx * dx + dy * dy;
        const float dw = sqrtf(q[2]) - sqrtf(tq[2]);
        const float dh = sqrtf(q[3]) - sqrtf(tq[3]);
        const float lwh = dw * dw + dh * dh;
        const float dob = q[4] - miou;
        const float lobj = dob * dob;

        loss = obj * (5.0f * (lxy + lwh) + lobj + cls)
             + 0.5f * (1.0f - obj) * noobj;
    }

    // Warp reduce
    #pragma unroll
    for (int o = 16; o > 0; o >>= 1)
        loss += __shfl_xor_sync(0xffffffffu, loss, o);
    if ((tid & 31) == 0) warp_sums[tid >> 5] = loss;
    __syncthreads();

    if (tid == 0) {
        const float bsum = warp_sums[0] + warp_sums[1] + warp_sums[2] + warp_sums[3];
        atomicAdd(&g_acc, (double)bsum);
        __threadfence();
        const unsigned int ticket = atomicAdd(&g_counter, 1u);
        if (ticket == gridDim.x - 1u) {
            // Last block: all other blocks' g_acc contributions are visible
            // (their atomicAdd happens-before their counter increment).
            const double total = atomicAdd(&g_acc, 0.0);
            out[0] = (float)(total * inv_bs);
            // Reset for next graph replay.
            g_acc = 0.0;
            __threadfence();
            g_counter = 0u;
        }
    }
}

extern "C" void kernel_launch(void* const* d_in, const int* in_sizes, int n_in,
                              void* d_out, int out_size) {
    const float* pred = (const float*)d_in[0];
    const float* targ = (const float*)d_in[1];
    const long long n = (long long)in_sizes[0];
    const int total_cells = (int)(n / CH);               // bs * 49
    const int bs = total_cells / (S_GRID * S_GRID);
    const int grid = (total_cells + CELLS_PER_BLOCK - 1) / CELLS_PER_BLOCK;

    yolo_loss_kernel<<<grid, NTHREADS>>>(pred, targ, total_cells,
                                         (float*)d_out, 1.0 / (double)bs);
}

// round 3
// speedup vs baseline: 1.1817x; 1.1817x over previous
#include <cuda_runtime.h>
#include <cstdint>

// YOLO loss: pred/target (bs, 7, 7, 30) f32 -> scalar f32.
// Grid-strided, double-buffered cp.async pipeline: tile t+1's HBM->smem copies
// are in flight while tile t is computed, keeping DRAM busy through the
// per-tile compute/sync phases. Last-block finalize writes the scalar.

#define S_GRID 7
#define CH 30
#define TILE 128
#define NTHREADS 128
#define SFLOATS (TILE * CH)          // 3840 floats per tensor per stage
#define STAGE_FLOATS (2 * SFLOATS)   // pred + targ per stage
#define SMEM_BYTES (2 * STAGE_FLOATS * 4)   // 61440 B (2 stages)
#define MAX_BLOCKS 444               // 3 CTAs/SM * 148 SMs

__device__ double g_acc = 0.0;
__device__ unsigned int g_counter = 0u;

__device__ __forceinline__ void cp16(uint32_t dst, const void* src) {
    asm volatile("cp.async.cg.shared.global [%0], [%1], 16;" :: "r"(dst), "l"(src));
}

__device__ __forceinline__ void issue_tile(uint32_t smem_u32, int stage,
                                           const float4* __restrict__ p4,
                                           const float4* __restrict__ t4,
                                           long long tile)
{
    const float4* ps = p4 + tile * (SFLOATS / 4);
    const float4* ts = t4 + tile * (SFLOATS / 4);
    const uint32_t dp = smem_u32 + (uint32_t)stage * (STAGE_FLOATS * 4);
    const uint32_t dt = dp + SFLOATS * 4;
    #pragma unroll
    for (int i = threadIdx.x; i < SFLOATS / 4; i += NTHREADS) {
        cp16(dp + 16u * (uint32_t)i, ps + i);
        cp16(dt + 16u * (uint32_t)i, ts + i);
    }
}

// Per-cell loss; p/t point at 30 contiguous floats (smem or gmem).
__device__ __forceinline__ float cell_loss(const float* __restrict__ p,
                                           const float* __restrict__ t)
{
    const float obj = (t[4] > 0.0f) ? 1.0f : 0.0f;

    const float dn0 = p[4] - t[4];
    const float dn1 = p[9] - t[9];
    const float noobj = dn0 * dn0 + dn1 * dn1;

    float cls = 0.0f;
    #pragma unroll
    for (int k = 10; k < 30; k++) {
        const float d = p[k] - t[k];
        cls = fmaf(d, d, cls);
    }

    const float invS = 1.0f / (float)S_GRID;
    const float tx = t[0] * invS, ty = t[1] * invS;
    const float tw = t[2], th = t[3];
    const float tx0 = tx - 0.5f * tw, tx1 = tx + 0.5f * tw;
    const float ty0 = ty - 0.5f * th, ty1 = ty + 0.5f * th;
    const float area_t = tw * th;

    float iou0 = 0.0f, iou1 = 0.0f;
    #pragma unroll
    for (int b = 0; b < 2; b++) {
        const float* q = p + 5 * b;
        const float px = q[0] * invS, py = q[1] * invS;
        const float pw = q[2], ph = q[3];
        const float lx = fmaxf(px - 0.5f * pw, tx0);
        const float rx = fminf(px + 0.5f * pw, tx1);
        const float ly = fmaxf(py - 0.5f * ph, ty0);
        const float ry = fminf(py + 0.5f * ph, ty1);
        const float wx = fmaxf(rx - lx, 0.0f);
        const float wy = fmaxf(ry - ly, 0.0f);
        const float inter = wx * wy;
        const float uni = fmaxf(pw * ph + area_t - inter, 1e-10f);
        const float iou = inter / uni;
        if (b == 0) iou0 = iou; else iou1 = iou;
    }
    // jnp.argmax picks first max -> box 1 only on strict greater.
    const int rb = (iou1 > iou0) ? 1 : 0;
    const float miou = fmaxf(iou0, iou1);

    const float* q  = p + 5 * rb;
    const float* tq = t + 5 * rb;
    const float dx = q[0] - tq[0];
    const float dy = q[1] - tq[1];
    const float lxy = dx * dx + dy * dy;
    const float dw = sqrtf(q[2]) - sqrtf(tq[2]);
    const float dh = sqrtf(q[3]) - sqrtf(tq[3]);
    const float lwh = dw * dw + dh * dh;
    const float dob = q[4] - miou;
    const float lobj = dob * dob;

    return obj * (5.0f * (lxy + lwh) + lobj + cls)
         + 0.5f * (1.0f - obj) * noobj;
}

__global__ __launch_bounds__(NTHREADS) void yolo_loss_kernel(
    const float* __restrict__ pred,
    const float* __restrict__ targ,
    int total_cells,
    float* __restrict__ out,
    double inv_bs)
{
    extern __shared__ float smem[];
    __shared__ float warp_sums[NTHREADS / 32];

    const int tid = threadIdx.x;
    const uint32_t smem_u32 = (uint32_t)__cvta_generic_to_shared(smem);
    const float4* p4 = (const float4*)pred;
    const float4* t4 = (const float4*)targ;

    const int ntiles = total_cells / TILE;
    const int rem = total_cells % TILE;

    float loss = 0.0f;
    long long t = blockIdx.x;
    int stage = 0;

    if (t < ntiles)
        issue_tile(smem_u32, 0, p4, t4, t);
    asm volatile("cp.async.commit_group;" ::: "memory");

    for (; t < ntiles; t += gridDim.x) {
        const long long tn = t + gridDim.x;
        if (tn < ntiles)
            issue_tile(smem_u32, stage ^ 1, p4, t4, tn);
        asm volatile("cp.async.commit_group;" ::: "memory");
        asm volatile("cp.async.wait_group 1;" ::: "memory");
        __syncthreads();

        const float* p = smem + stage * STAGE_FLOATS + tid * CH;
        const float* tt = smem + stage * STAGE_FLOATS + SFLOATS + tid * CH;
        loss += cell_loss(p, tt);

        __syncthreads();   // protect stage buffer before next overwrite
        stage ^= 1;
    }

    // Tail cells (total_cells % TILE), handled by block 0 straight from gmem.
    if (rem && blockIdx.x == 0 && tid < rem) {
        const long long c = (long long)ntiles * TILE + tid;
        loss += cell_loss(pred + c * CH, targ + c * CH);
    }

    // Block reduction
    #pragma unroll
    for (int o = 16; o > 0; o >>= 1)
        loss += __shfl_xor_sync(0xffffffffu, loss, o);
    if ((tid & 31) == 0) warp_sums[tid >> 5] = loss;
    __syncthreads();

    if (tid == 0) {
        const float bsum = warp_sums[0] + warp_sums[1] + warp_sums[2] + warp_sums[3];
        atomicAdd(&g_acc, (double)bsum);
        __threadfence();
        const unsigned int ticket = atomicAdd(&g_counter, 1u);
        if (ticket == gridDim.x - 1u) {
            const double total = atomicAdd(&g_acc, 0.0);
            out[0] = (float)(total * inv_bs);
            g_acc = 0.0;          // reset for next graph replay
            __threadfence();
            g_counter = 0u;
        }
    }
}

extern "C" void kernel_launch(void* const* d_in, const int* in_sizes, int n_in,
                              void* d_out, int out_size) {
    const float* pred = (const float*)d_in[0];
    const float* targ = (const float*)d_in[1];
    const long long n = (long long)in_sizes[0];
    const int total_cells = (int)(n / CH);            // bs * 49
    const int bs = total_cells / (S_GRID * S_GRID);
    const int ntiles = total_cells / TILE;

    int grid = ntiles < MAX_BLOCKS ? ntiles : MAX_BLOCKS;
    if (grid < 1) grid = 1;

    cudaFuncSetAttribute(yolo_loss_kernel,
                         cudaFuncAttributeMaxDynamicSharedMemorySize, SMEM_BYTES);
    yolo_loss_kernel<<<grid, NTHREADS, SMEM_BYTES>>>(pred, targ, total_cells,
                                                     (float*)d_out,
                                                     1.0 / (double)bs);
}